// round 3
// baseline (speedup 1.0000x reference)
#include <cuda_runtime.h>

// ---------------------------------------------------------------------------
// ImplicitMeshDecoder: fused coordinate-MLP
//   rows M = B*P = 2 * 64^3 = 524288, hidden H = 512
//   layer0: silu(latb0[b] + x*Wc0 + y*Wc1 + z*Wc2)   (analytic coords)
//   layer1: silu(h @ W1 + b1)   512x512 GEMM
//   layer2: silu(h @ W2 + b2)   512x512 GEMM
//   layer3: h @ W3 + b3         512->1
// Strategy: one CTA per 64-row tile; activations live in SMEM (128 KB);
// weights streamed in 8-row k-tiles (double-buffered, 32 KB); 8x8 register
// blocking per thread with packed fma.rn.f32x2 (Blackwell 2x fp32 rate).
// ---------------------------------------------------------------------------

#define HDIM     512
#define MTILE    64
#define NTHREADS 512
#define KT       8
#define PGRID    262144    // 64^3
#define BATCH    2
#define NBLOCKS  ((BATCH * PGRID) / MTILE)   // 8192

__device__ float g_latb0[BATCH * HDIM];

// ---- packed f32x2 helpers --------------------------------------------------
__device__ __forceinline__ void fma2(unsigned long long& d,
                                     unsigned long long a,
                                     unsigned long long b) {
    asm("fma.rn.f32x2 %0, %1, %2, %0;" : "+l"(d) : "l"(a), "l"(b));
}
__device__ __forceinline__ unsigned long long pack2(float v) {
    unsigned long long r;
    asm("mov.b64 %0, {%1, %1};" : "=l"(r) : "f"(v));
    return r;
}
__device__ __forceinline__ void unpack2(unsigned long long v, float& lo, float& hi) {
    asm("mov.b64 {%0, %1}, %2;" : "=f"(lo), "=f"(hi) : "l"(v));
}

__device__ __forceinline__ float silu(float v) {
    // v / (1 + e^-v); MUFU-based, ~1e-6 rel err, saturates correctly at +/-inf
    return __fdividef(v, 1.0f + __expf(-v));
}

// ---- pre-kernel: latb0[b][h] = cad_latent[b] @ W0[:512] + b0 ---------------
__global__ void latb0_kernel(const float* __restrict__ lat,
                             const float* __restrict__ W0,
                             const float* __restrict__ b0) {
    int b = blockIdx.x;          // 2 blocks
    int h = threadIdx.x;         // 512 threads
    const float* L = lat + b * HDIM;
    float acc = b0[h];
#pragma unroll 8
    for (int d = 0; d < HDIM; d++)
        acc = fmaf(L[d], W0[d * HDIM + h], acc);
    g_latb0[b * HDIM + h] = acc;
}

// ---- main fused kernel -----------------------------------------------------
__global__ __launch_bounds__(NTHREADS, 1)
void mlp_fused_kernel(const float* __restrict__ W0,   // (515, 512)
                      const float* __restrict__ W1,
                      const float* __restrict__ b1,
                      const float* __restrict__ W2,
                      const float* __restrict__ b2,
                      const float* __restrict__ W3,   // (512, 1)
                      const float* __restrict__ b3,
                      float* __restrict__ out) {
    extern __shared__ float smem[];
    float* sh = smem;                        // MTILE * HDIM activations
    float* sw = smem + MTILE * HDIM;         // 2 * KT * HDIM weight stage

    const int tid = threadIdx.x;
    const int tx  = tid & 63;    // column group: cols n = tx*2 + 128*jp (+0/1)
    const int ty  = tid >> 6;    // row group:    rows m = ty*8 + i
    const int m0  = blockIdx.x * MTILE;

    // ---------------- layer 0: analytic coords + latent ----------------
    {
        const float* Wc = W0 + (size_t)HDIM * HDIM;   // rows 512..514 of W0
        const int b = m0 >> 18;                       // P = 2^18; tile never crosses batch
        // hoist per-column weight/latent loads (shared by the 8 rows)
        float latv[8], c0[8], c1[8], c2[8];
#pragma unroll
        for (int jp = 0; jp < 4; jp++) {
#pragma unroll
            for (int c = 0; c < 2; c++) {
                int n = tx * 2 + 128 * jp + c;
                latv[jp * 2 + c] = g_latb0[b * HDIM + n];
                c0[jp * 2 + c]   = Wc[n];
                c1[jp * 2 + c]   = Wc[HDIM + n];
                c2[jp * 2 + c]   = Wc[2 * HDIM + n];
            }
        }
#pragma unroll
        for (int i = 0; i < 8; i++) {
            int mg = m0 + ty * 8 + i;
            int p  = mg & (PGRID - 1);
            float x = -1.2f + (float)(p >> 12)        * (2.4f / 63.0f);
            float y = -1.2f + (float)((p >> 6) & 63)  * (2.4f / 63.0f);
            float z = -1.2f + (float)(p & 63)         * (2.4f / 63.0f);
            float* row = sh + (ty * 8 + i) * HDIM;
#pragma unroll
            for (int q = 0; q < 8; q++) {
                int n = tx * 2 + 128 * (q >> 1) + (q & 1);
                float pre = latv[q];
                pre = fmaf(x, c0[q], pre);
                pre = fmaf(y, c1[q], pre);
                pre = fmaf(z, c2[q], pre);
                row[n] = silu(pre);
            }
        }
    }
    __syncthreads();

    // ---------------- layers 1 & 2: 512x512 GEMM + silu ----------------
    const float* Ws[2] = {W1, W2};
    const float* Bs[2] = {b1, b2};

    for (int layer = 0; layer < 2; layer++) {
        const float*  W  = Ws[layer];
        const float*  bv = Bs[layer];
        const float4* W4 = (const float4*)W;

        unsigned long long acc[8][4];
#pragma unroll
        for (int i = 0; i < 8; i++)
#pragma unroll
            for (int jp = 0; jp < 4; jp++) acc[i][jp] = 0ull;

        // prologue: stage k-tile 0
        float4 r0 = __ldg(W4 + 0 * (KT * HDIM / 4) + tid);
        float4 r1 = __ldg(W4 + 0 * (KT * HDIM / 4) + (NTHREADS) + tid);
        ((float4*)sw)[tid]            = r0;
        ((float4*)sw)[NTHREADS + tid] = r1;
        __syncthreads();

        for (int t = 0; t < HDIM / KT; t++) {
            // prefetch next tile into registers (latency hidden by FFMA body)
            if (t < HDIM / KT - 1) {
                r0 = __ldg(W4 + (t + 1) * (KT * HDIM / 4) + tid);
                r1 = __ldg(W4 + (t + 1) * (KT * HDIM / 4) + NTHREADS + tid);
            }
            const float* wbase = sw + (t & 1) * (KT * HDIM);
            const float* hbase = sh + (ty * 8) * HDIM + t * KT;

#pragma unroll
            for (int kp = 0; kp < KT / 2; kp++) {
                float2 hv[8];
#pragma unroll
                for (int i = 0; i < 8; i++)  // broadcast LDS.64 within warp
                    hv[i] = *(const float2*)(hbase + i * HDIM + kp * 2);
#pragma unroll
                for (int kk = 0; kk < 2; kk++) {
                    unsigned long long w2[4];
#pragma unroll
                    for (int jp = 0; jp < 4; jp++)
                        w2[jp] = *(const unsigned long long*)
                                 (wbase + (kp * 2 + kk) * HDIM + tx * 2 + 128 * jp);
#pragma unroll
                    for (int i = 0; i < 8; i++) {
                        unsigned long long h2 = pack2(kk ? hv[i].y : hv[i].x);
#pragma unroll
                        for (int jp = 0; jp < 4; jp++)
                            fma2(acc[i][jp], h2, w2[jp]);
                    }
                }
            }

            if (t < HDIM / KT - 1) {
                float* dst = sw + ((t + 1) & 1) * (KT * HDIM);
                ((float4*)dst)[tid]            = r0;
                ((float4*)dst)[NTHREADS + tid] = r1;
            }
            __syncthreads();
        }

        // epilogue: bias + silu, write back to sh (safe: final sync above
        // guarantees every thread finished reading sh)
#pragma unroll
        for (int jp = 0; jp < 4; jp++) {
            int n0 = tx * 2 + 128 * jp;
            float2 bb = *(const float2*)(bv + n0);
#pragma unroll
            for (int i = 0; i < 8; i++) {
                float s0, s1;
                unpack2(acc[i][jp], s0, s1);
                s0 = silu(s0 + bb.x);
                s1 = silu(s1 + bb.y);
                *(float2*)(sh + (ty * 8 + i) * HDIM + n0) = make_float2(s0, s1);
            }
        }
        __syncthreads();
    }

    // ---------------- layer 3: 512 -> 1 dot ----------------
    {
        int r8  = tid & 7;        // 8 lanes cooperate per row
        int row = tid >> 3;       // 64 rows
        const float* hrow = sh + row * HDIM;
        float s = 0.0f;
#pragma unroll 8
        for (int c = 0; c < 64; c++) {
            int n = r8 + 8 * c;   // stride-8 to spread banks (<=4-way)
            s = fmaf(hrow[n], W3[n], s);
        }
        s += __shfl_down_sync(0xffffffffu, s, 4, 8);
        s += __shfl_down_sync(0xffffffffu, s, 2, 8);
        s += __shfl_down_sync(0xffffffffu, s, 1, 8);
        if (r8 == 0) out[m0 + row] = s + b3[0];
    }
}

// ---------------------------------------------------------------------------
extern "C" void kernel_launch(void* const* d_in, const int* in_sizes, int n_in,
                              void* d_out, int out_size) {
    const float* lat = (const float*)d_in[0];
    const float* W0  = (const float*)d_in[1];
    const float* b0  = (const float*)d_in[2];
    const float* W1  = (const float*)d_in[3];
    const float* b1  = (const float*)d_in[4];
    const float* W2  = (const float*)d_in[5];
    const float* b2  = (const float*)d_in[6];
    const float* W3  = (const float*)d_in[7];
    const float* b3  = (const float*)d_in[8];
    float* out = (float*)d_out;

    latb0_kernel<<<BATCH, HDIM>>>(lat, W0, b0);

    size_t smem = (size_t)(MTILE * HDIM + 2 * KT * HDIM) * sizeof(float); // 160 KB
    cudaFuncSetAttribute(mlp_fused_kernel,
                         cudaFuncAttributeMaxDynamicSharedMemorySize, (int)smem);
    mlp_fused_kernel<<<NBLOCKS, NTHREADS, smem>>>(W0, W1, b1, W2, b2, W3, b3, out);
}

// round 6
// speedup vs baseline: 5.3767x; 5.3767x over previous
#include <cuda_runtime.h>
#include <cuda_fp16.h>
#include <cstdint>

// ---------------------------------------------------------------------------
// ImplicitMeshDecoder via warp-level HMMA (mma.sync m16n8k16, fp16->fp32).
// (tcgen05 unusable: harness emits PTX .target sm_103 without the 'a' suffix.)
//   M = 524288 rows, H = 512.  Per CTA: 64 rows.
//   layer0 : analytic coords + latent  -> silu -> A_in (SMEM fp16, XOR-swizzled)
//   layer1 : A_in @ W1 + b1  (HMMA)    -> silu -> A_out
//   layer2 : A_out @ W2 + b2 (HMMA)    -> silu -> dot W3 (reg-folded) -> out
// Weights pre-transposed (W^T, n-major k-contiguous), fp16-converted and
// XOR-swizzled by a prep kernel into GMEM chunk images (256n x 64k = 32KB),
// double-buffered through SMEM with reg-staged prefetch.
// ---------------------------------------------------------------------------

#define HDIM   512
#define MT     64
#define NT     512
#define PGRID  262144
#define BATCH  2
#define NCTA   ((BATCH * PGRID) / MT)    // 8192
#define CHUNK_HALFS 16384                // 256n * 64k
#define CHUNK_F4    2048                 // 32KB / 16B

__device__ float  g_latb0[BATCH * HDIM];
__device__ __half g_wprep[4 * 8 * CHUNK_HALFS];  // [pass(l,nh)][kchunk][32KB image]

// ---- helpers ---------------------------------------------------------------
static __device__ __forceinline__ uint32_t smem_u32(const void* p) {
    uint32_t a;
    asm("{ .reg .u64 t; cvta.to.shared.u64 t, %1; cvt.u32.u64 %0, t; }"
        : "=r"(a) : "l"(p));
    return a;
}
static __device__ __forceinline__ float silu(float v) {
    // exact-form silu: v / (1 + e^-v).  tanh.approx is NOT accurate enough
    // (abs err ~1e-3 scale) for the 1e-3 gate on top of fp16 GEMM error.
    return __fdividef(v, 1.0f + __expf(-v));
}
// A tile (64 x 512 fp16, 1024B rows): byte for (r, k); XOR-permute 16B columns
static __device__ __forceinline__ uint32_t a_off(int r, int k) {
    return (uint32_t)(r * 1024) + (uint32_t)((((k >> 3) ^ (r & 7)) << 4))
         + (uint32_t)((k & 7) * 2);
}
// W chunk image (256n x 64k fp16, 128B rows): byte for (n, k)
static __device__ __forceinline__ uint32_t w_off(int n, int k) {
    return (uint32_t)(n * 128) + (uint32_t)(((k >> 3) ^ (n & 7)) << 4)
         + (uint32_t)((k & 7) * 2);
}

#define LDSM4(r0, r1, r2, r3, addr)                                        \
    asm volatile("ldmatrix.sync.aligned.m8n8.x4.shared.b16 "               \
                 "{%0,%1,%2,%3}, [%4];"                                    \
                 : "=r"(r0), "=r"(r1), "=r"(r2), "=r"(r3) : "r"(addr))

#define MMA16816(d, a0, a1, a2, a3, b0, b1)                                \
    asm volatile("mma.sync.aligned.m16n8k16.row.col.f32.f16.f16.f32 "      \
                 "{%0,%1,%2,%3}, {%4,%5,%6,%7}, {%8,%9}, {%0,%1,%2,%3};"   \
                 : "+f"((d)[0]), "+f"((d)[1]), "+f"((d)[2]), "+f"((d)[3])  \
                 : "r"(a0), "r"(a1), "r"(a2), "r"(a3), "r"(b0), "r"(b1))

// ---- prep: latb0 = latent @ W0[:512] + b0 ----------------------------------
__global__ void latb0_kernel(const float* __restrict__ lat,
                             const float* __restrict__ W0,
                             const float* __restrict__ b0) {
    int b = blockIdx.x, h = threadIdx.x;
    const float* L = lat + b * HDIM;
    float acc = b0[h];
#pragma unroll 8
    for (int d = 0; d < HDIM; d++) acc = fmaf(L[d], W0[d * HDIM + h], acc);
    g_latb0[b * HDIM + h] = acc;
}

// ---- prep: W^T + fp16 + swizzle into chunk images --------------------------
// pass = l*2 + nh; chunk (pass, kc) holds WT[n = nh*256 + nn][k = kc*64 + kk]
__global__ void wprep_kernel(const float* __restrict__ W1,
                             const float* __restrict__ W2) {
    int idx = blockIdx.x * blockDim.x + threadIdx.x;   // 0 .. 2*512*512-1
    int l = idx >> 18, rem = idx & 262143;
    int k = rem >> 9, n = rem & 511;                   // source: W[k][n]
    float w = (l ? W2 : W1)[rem];
    int nh = n >> 8, nn = n & 255, kc = k >> 6, kk = k & 63;
    int chunk = (l * 2 + nh) * 8 + kc;
    g_wprep[(size_t)chunk * CHUNK_HALFS + (w_off(nn, kk) >> 1)] = __float2half_rn(w);
}

// ---- main fused kernel -----------------------------------------------------
__global__ __launch_bounds__(NT, 1)
void mlp_hmma_kernel(const float* __restrict__ W0,
                     const float* __restrict__ b1,
                     const float* __restrict__ b2,
                     const float* __restrict__ W3,
                     const float* __restrict__ b3,
                     float* __restrict__ out) {
    extern __shared__ char dyn[];
    uint32_t sbase = smem_u32(dyn);
    uint32_t s0 = (sbase + 1023u) & ~1023u;
    char* base = dyn + (s0 - sbase);

    char*  sAin  = base;                       // 65536
    char*  sAout = base + 65536;               // 65536
    char*  sWb[2] = { base + 131072, base + 163840 };   // 2 x 32768
    float* sW3   = (float*)(base + 196608);    // 2048
    float* sB1   = (float*)(base + 198656);    // 2048
    float* sB2   = (float*)(base + 200704);    // 2048
    float* spart = (float*)(base + 202752);    // 2048
    float* sb3   = (float*)(base + 204800);
    const uint32_t u_Ain = s0, u_Aout = s0 + 65536;
    const uint32_t u_W[2] = { s0 + 131072, s0 + 163840 };

    const int tid  = threadIdx.x;
    const int lane = tid & 31, wid = tid >> 5;
    const int wm   = wid >> 3;                 // 0..1 : rows wm*32
    const int wn   = wid & 7;                  // 0..7 : cols wn*32 (in 256)
    const int m0   = blockIdx.x * MT;

    sW3[tid] = W3[tid];
    sB1[tid] = b1[tid];
    sB2[tid] = b2[tid];
    if (tid == 0) *sb3 = b3[0];

    // -------- layer 0: analytic coords + latent -> silu -> A_in --------
    {
        const float* Wc = W0 + (size_t)HDIM * HDIM;
        const int b  = m0 >> 18;
        const int n  = (tid & 255) * 2;
        const int rh = tid >> 8;               // rows rh*32 + i
        float la0 = g_latb0[b * HDIM + n],     la1 = g_latb0[b * HDIM + n + 1];
        float c00 = Wc[n],            c01 = Wc[n + 1];
        float c10 = Wc[HDIM + n],     c11 = Wc[HDIM + n + 1];
        float c20 = Wc[2 * HDIM + n], c21 = Wc[2 * HDIM + n + 1];
#pragma unroll 4
        for (int i = 0; i < 32; i++) {
            int r = rh * 32 + i;
            int p = (m0 + r) & (PGRID - 1);
            float x = -1.2f + (float)(p >> 12)       * (2.4f / 63.0f);
            float y = -1.2f + (float)((p >> 6) & 63) * (2.4f / 63.0f);
            float z = -1.2f + (float)(p & 63)        * (2.4f / 63.0f);
            float v0 = silu(fmaf(x, c00, fmaf(y, c10, fmaf(z, c20, la0))));
            float v1 = silu(fmaf(x, c01, fmaf(y, c11, fmaf(z, c21, la1))));
            *(__half2*)(sAin + a_off(r, n)) = __floats2half2_rn(v0, v1);
        }
    }

    // per-lane ldmatrix row/col components (invariant across passes)
    const int mr0 = wm * 32 + (lane & 15);            // A frag mg=0 row
    const int mr1 = mr0 + 16;                         // mg=1
    const int ka  = lane >> 4;                        // A k-block offset (8s)
    const int nr0 = wn * 32 + (lane & 7) + ((lane >> 4) << 3);   // B pair 0
    const int nr1 = nr0 + 16;                                     // B pair 1
    const int kb  = (lane >> 3) & 1;                  // B k-block offset
    const uint32_t aRow0 = (uint32_t)(mr0 * 1024), aRow1 = (uint32_t)(mr1 * 1024);
    const int am0 = mr0 & 7, am1 = mr1 & 7;
    const uint32_t bRow0 = (uint32_t)(nr0 * 128), bRow1 = (uint32_t)(nr1 * 128);
    const int bn0 = nr0 & 7, bn1 = nr1 & 7;

    float pr[2][2] = {{0.f, 0.f}, {0.f, 0.f}};        // layer-2 row partials

    for (int pass = 0; pass < 4; pass++) {
        const int l  = pass >> 1, nh = pass & 1;
        const float4* wp = (const float4*)g_wprep + (size_t)pass * 8 * CHUNK_F4;
        const uint32_t u_A = (l == 0) ? u_Ain : u_Aout;

        float acc[2][4][4];
#pragma unroll
        for (int mg = 0; mg < 2; mg++)
#pragma unroll
            for (int ng = 0; ng < 4; ng++)
#pragma unroll
                for (int i = 0; i < 4; i++) acc[mg][ng][i] = 0.f;

        // stage chunk 0 (sync also orders layer0 / previous epilogue writes)
        {
            float4 r0 = __ldg(wp + tid),        r1 = __ldg(wp + tid + 512);
            float4 r2 = __ldg(wp + tid + 1024), r3 = __ldg(wp + tid + 1536);
            float4* d = (float4*)sWb[0];
            d[tid] = r0; d[tid + 512] = r1; d[tid + 1024] = r2; d[tid + 1536] = r3;
        }
        __syncthreads();

        for (int c = 0; c < 8; c++) {
            float4 r0, r1, r2, r3;
            if (c < 7) {
                const float4* p = wp + (size_t)(c + 1) * CHUNK_F4;
                r0 = __ldg(p + tid);        r1 = __ldg(p + tid + 512);
                r2 = __ldg(p + tid + 1024); r3 = __ldg(p + tid + 1536);
            }
            const uint32_t wb = u_W[c & 1];
#pragma unroll
            for (int ks = 0; ks < 4; ks++) {
                const int kbA = c * 8 + ks * 2 + ka;      // global k>>3
                const int kbB = ks * 2 + kb;              // chunk-local k>>3
                uint32_t a0r[4], a1r[4], b0r[4], b1r[4];
                LDSM4(a0r[0], a0r[1], a0r[2], a0r[3],
                      u_A + aRow0 + (uint32_t)((kbA ^ am0) << 4));
                LDSM4(a1r[0], a1r[1], a1r[2], a1r[3],
                      u_A + aRow1 + (uint32_t)((kbA ^ am1) << 4));
                LDSM4(b0r[0], b0r[1], b0r[2], b0r[3],
                      wb + bRow0 + (uint32_t)((kbB ^ bn0) << 4));
                LDSM4(b1r[0], b1r[1], b1r[2], b1r[3],
                      wb + bRow1 + (uint32_t)((kbB ^ bn1) << 4));
#pragma unroll
                for (int mg = 0; mg < 2; mg++) {
                    uint32_t* a = mg ? a1r : a0r;
                    MMA16816(acc[mg][0], a[0], a[1], a[2], a[3], b0r[0], b0r[1]);
                    MMA16816(acc[mg][1], a[0], a[1], a[2], a[3], b0r[2], b0r[3]);
                    MMA16816(acc[mg][2], a[0], a[1], a[2], a[3], b1r[0], b1r[1]);
                    MMA16816(acc[mg][3], a[0], a[1], a[2], a[3], b1r[2], b1r[3]);
                }
            }
            if (c < 7) {
                float4* d = (float4*)sWb[(c + 1) & 1];
                d[tid] = r0; d[tid + 512] = r1; d[tid + 1024] = r2; d[tid + 1536] = r3;
            }
            __syncthreads();
        }

        // -------- epilogue (adds layer bias, then silu) --------
        if (l == 0) {
#pragma unroll
            for (int mg = 0; mg < 2; mg++) {
                int rbase = wm * 32 + mg * 16 + (lane >> 2);
#pragma unroll
                for (int ng = 0; ng < 4; ng++) {
                    int nc = nh * 256 + wn * 32 + ng * 8 + 2 * (lane & 3);
                    float bb0 = sB1[nc], bb1 = sB1[nc + 1];
                    float v0 = silu(acc[mg][ng][0] + bb0);
                    float v1 = silu(acc[mg][ng][1] + bb1);
                    *(__half2*)(sAout + a_off(rbase, nc)) = __floats2half2_rn(v0, v1);
                    v0 = silu(acc[mg][ng][2] + bb0);
                    v1 = silu(acc[mg][ng][3] + bb1);
                    *(__half2*)(sAout + a_off(rbase + 8, nc)) = __floats2half2_rn(v0, v1);
                }
            }
        } else {
            // bias + silu + W3 dot folded into row partials (no SMEM round-trip)
#pragma unroll
            for (int mg = 0; mg < 2; mg++)
#pragma unroll
                for (int ng = 0; ng < 4; ng++) {
                    int nc = nh * 256 + wn * 32 + ng * 8 + 2 * (lane & 3);
                    float bb0 = sB2[nc], bb1 = sB2[nc + 1];
                    float w0 = sW3[nc],  w1 = sW3[nc + 1];
                    pr[mg][0] = fmaf(silu(acc[mg][ng][0] + bb0), w0, pr[mg][0]);
                    pr[mg][0] = fmaf(silu(acc[mg][ng][1] + bb1), w1, pr[mg][0]);
                    pr[mg][1] = fmaf(silu(acc[mg][ng][2] + bb0), w0, pr[mg][1]);
                    pr[mg][1] = fmaf(silu(acc[mg][ng][3] + bb1), w1, pr[mg][1]);
                }
        }
        __syncthreads();
    }

    // -------- final reduction: lanes (cols) -> warps (wn) -> rows --------
#pragma unroll
    for (int mg = 0; mg < 2; mg++)
#pragma unroll
        for (int h = 0; h < 2; h++) {
            float v = pr[mg][h];
            v += __shfl_xor_sync(0xffffffffu, v, 1);
            v += __shfl_xor_sync(0xffffffffu, v, 2);
            if ((lane & 3) == 0) {
                int r = wm * 32 + mg * 16 + (lane >> 2) + 8 * h;
                spart[r * 8 + wn] = v;
            }
        }
    __syncthreads();
    if (tid < MT) {
        float s = *sb3;
#pragma unroll
        for (int w = 0; w < 8; w++) s += spart[tid * 8 + w];
        out[m0 + tid] = s;
    }
}

// ---------------------------------------------------------------------------
extern "C" void kernel_launch(void* const* d_in, const int* in_sizes, int n_in,
                              void* d_out, int out_size) {
    const float* lat = (const float*)d_in[0];
    const float* W0  = (const float*)d_in[1];
    const float* b0  = (const float*)d_in[2];
    const float* W1  = (const float*)d_in[3];
    const float* b1  = (const float*)d_in[4];
    const float* W2  = (const float*)d_in[5];
    const float* b2  = (const float*)d_in[6];
    const float* W3  = (const float*)d_in[7];
    const float* b3  = (const float*)d_in[8];
    float* out = (float*)d_out;

    latb0_kernel<<<BATCH, HDIM>>>(lat, W0, b0);
    wprep_kernel<<<1024, 512>>>(W1, W2);

    size_t smem = 1024 + 204800 + 64;   // align slack + tiles + scalars
    cudaFuncSetAttribute(mlp_hmma_kernel,
                         cudaFuncAttributeMaxDynamicSharedMemorySize, (int)smem);
    mlp_hmma_kernel<<<NCTA, NT, smem>>>(W0, b1, b2, W3, b3, out);
}

// round 7
// speedup vs baseline: 6.5867x; 1.2250x over previous
#include <cuda_runtime.h>
#include <cuda_fp16.h>
#include <cstdint>

// ---------------------------------------------------------------------------
// ImplicitMeshDecoder via warp-level HMMA (mma.sync m16n8k16, fp16->fp32).
//   M = 524288 rows, H = 512.  Per CTA: 64 rows, 256 threads (8 warps).
//   Warp tile 32m x 64n (was 32x32): SMEM crossbar bytes/FLOP -25%.
//   Weight chunks staged with cp.async (no register round-trip).
//   layer0 : analytic coords + latent  -> silu -> A_in (SMEM fp16, XOR-swz)
//   layer1 : A_in @ W1 + b1  (HMMA)    -> silu -> A_out
//   layer2 : A_out @ W2 + b2 (HMMA)    -> silu -> dot W3 (reg-folded) -> out
// ---------------------------------------------------------------------------

#define HDIM   512
#define MT     64
#define NT     256
#define PGRID  262144
#define BATCH  2
#define NCTA   ((BATCH * PGRID) / MT)    // 8192
#define CHUNK_HALFS 16384                // 256n * 64k
#define CHUNK_BYTES 32768

__device__ float  g_latb0[BATCH * HDIM];
__device__ __align__(16) __half g_wprep[4 * 8 * CHUNK_HALFS]; // [pass][kchunk][32KB]

// ---- helpers ---------------------------------------------------------------
static __device__ __forceinline__ uint32_t smem_u32(const void* p) {
    uint32_t a;
    asm("{ .reg .u64 t; cvta.to.shared.u64 t, %1; cvt.u32.u64 %0, t; }"
        : "=r"(a) : "l"(p));
    return a;
}
static __device__ __forceinline__ float silu(float v) {
    // exact-form silu (tanh.approx's ~1e-3 abs error would eat the gate)
    return __fdividef(v, 1.0f + __expf(-v));
}
// A tile (64 x 512 fp16, 1024B rows): byte for (r, k); XOR-permute 16B columns
static __device__ __forceinline__ uint32_t a_off(int r, int k) {
    return (uint32_t)(r * 1024) + (uint32_t)((((k >> 3) ^ (r & 7)) << 4))
         + (uint32_t)((k & 7) * 2);
}
// W chunk image (256n x 64k fp16, 128B rows): byte for (n, k)
static __device__ __forceinline__ uint32_t w_off(int n, int k) {
    return (uint32_t)(n * 128) + (uint32_t)(((k >> 3) ^ (n & 7)) << 4)
         + (uint32_t)((k & 7) * 2);
}

#define LDSM4(r0, r1, r2, r3, addr)                                        \
    asm volatile("ldmatrix.sync.aligned.m8n8.x4.shared.b16 "               \
                 "{%0,%1,%2,%3}, [%4];"                                    \
                 : "=r"(r0), "=r"(r1), "=r"(r2), "=r"(r3) : "r"(addr))

#define MMA16816(d, a0, a1, a2, a3, b0, b1)                                \
    asm volatile("mma.sync.aligned.m16n8k16.row.col.f32.f16.f16.f32 "      \
                 "{%0,%1,%2,%3}, {%4,%5,%6,%7}, {%8,%9}, {%0,%1,%2,%3};"   \
                 : "+f"((d)[0]), "+f"((d)[1]), "+f"((d)[2]), "+f"((d)[3])  \
                 : "r"(a0), "r"(a1), "r"(a2), "r"(a3), "r"(b0), "r"(b1))

#define CP16(dst, src) asm volatile(                                       \
    "cp.async.cg.shared.global [%0], [%1], 16;" :: "r"(dst), "l"(src))
#define CPCOMMIT() asm volatile("cp.async.commit_group;" ::: "memory")
#define CPWAIT0()  asm volatile("cp.async.wait_group 0;" ::: "memory")

// ---- prep: latb0 = latent @ W0[:512] + b0 ----------------------------------
__global__ void latb0_kernel(const float* __restrict__ lat,
                             const float* __restrict__ W0,
                             const float* __restrict__ b0) {
    int b = blockIdx.x, h = threadIdx.x;
    const float* L = lat + b * HDIM;
    float a0 = 0.f, a1 = 0.f, a2 = 0.f, a3 = 0.f;   // 4-way ILP
#pragma unroll 4
    for (int d = 0; d < HDIM; d += 4) {
        a0 = fmaf(L[d],     W0[(d)     * HDIM + h], a0);
        a1 = fmaf(L[d + 1], W0[(d + 1) * HDIM + h], a1);
        a2 = fmaf(L[d + 2], W0[(d + 2) * HDIM + h], a2);
        a3 = fmaf(L[d + 3], W0[(d + 3) * HDIM + h], a3);
    }
    g_latb0[b * HDIM + h] = b0[h] + ((a0 + a1) + (a2 + a3));
}

// ---- prep: W^T + fp16 + swizzle into chunk images --------------------------
// pass = l*2 + nh; chunk (pass, kc) holds WT[n = nh*256 + nn][k = kc*64 + kk]
__global__ void wprep_kernel(const float* __restrict__ W1,
                             const float* __restrict__ W2) {
    int idx = blockIdx.x * blockDim.x + threadIdx.x;   // 0 .. 2*512*512-1
    int l = idx >> 18, rem = idx & 262143;
    int k = rem >> 9, n = rem & 511;                   // source: W[k][n]
    float w = (l ? W2 : W1)[rem];
    int nh = n >> 8, nn = n & 255, kc = k >> 6, kk = k & 63;
    int chunk = (l * 2 + nh) * 8 + kc;
    g_wprep[(size_t)chunk * CHUNK_HALFS + (w_off(nn, kk) >> 1)] = __float2half_rn(w);
}

// ---- main fused kernel -----------------------------------------------------
__global__ __launch_bounds__(NT, 1)
void mlp_hmma_kernel(const float* __restrict__ W0,
                     const float* __restrict__ b1,
                     const float* __restrict__ b2,
                     const float* __restrict__ W3,
                     const float* __restrict__ b3,
                     float* __restrict__ out) {
    extern __shared__ char dyn[];
    uint32_t sbase = smem_u32(dyn);
    uint32_t s0 = (sbase + 1023u) & ~1023u;
    char* base = dyn + (s0 - sbase);

    char*  sAin  = base;                       // 65536
    char*  sAout = base + 65536;               // 65536
    float* sW3   = (float*)(base + 196608);    // 2048
    float* sB1   = (float*)(base + 198656);    // 2048
    float* sB2   = (float*)(base + 200704);    // 2048
    float* spart = (float*)(base + 202752);    // 1024 (64 rows x 4 wn)
    float* sb3   = (float*)(base + 203776);
    const uint32_t u_Ain = s0, u_Aout = s0 + 65536;
    const uint32_t u_W[2] = { s0 + 131072, s0 + 163840 };

    const int tid  = threadIdx.x;
    const int lane = tid & 31, wid = tid >> 5;
    const int wm   = wid >> 2;                 // 0..1 : rows wm*32
    const int wn   = wid & 3;                  // 0..3 : cols wn*64 (in 256)
    const int m0   = blockIdx.x * MT;

    sW3[tid] = W3[tid];  sW3[tid + 256] = W3[tid + 256];
    sB1[tid] = b1[tid];  sB1[tid + 256] = b1[tid + 256];
    sB2[tid] = b2[tid];  sB2[tid + 256] = b2[tid + 256];
    if (tid == 0) *sb3 = b3[0];

    // -------- layer 0: analytic coords + latent -> silu -> A_in --------
    {
        const float* Wc = W0 + (size_t)HDIM * HDIM;
        const int b = m0 >> 18;
        const int n = tid * 2;                 // 256 threads x col-pair
        float la0 = g_latb0[b * HDIM + n],     la1 = g_latb0[b * HDIM + n + 1];
        float c00 = Wc[n],            c01 = Wc[n + 1];
        float c10 = Wc[HDIM + n],     c11 = Wc[HDIM + n + 1];
        float c20 = Wc[2 * HDIM + n], c21 = Wc[2 * HDIM + n + 1];
#pragma unroll 4
        for (int r = 0; r < MT; r++) {
            int p = (m0 + r) & (PGRID - 1);
            float x = -1.2f + (float)(p >> 12)       * (2.4f / 63.0f);
            float y = -1.2f + (float)((p >> 6) & 63) * (2.4f / 63.0f);
            float z = -1.2f + (float)(p & 63)        * (2.4f / 63.0f);
            float v0 = silu(fmaf(x, c00, fmaf(y, c10, fmaf(z, c20, la0))));
            float v1 = silu(fmaf(x, c01, fmaf(y, c11, fmaf(z, c21, la1))));
            *(__half2*)(sAin + a_off(r, n)) = __floats2half2_rn(v0, v1);
        }
    }

    // per-lane ldmatrix addressing (invariant across passes)
    const int x7  = lane & 7;                  // XOR term (== row&7 everywhere)
    const int ka  = lane >> 4;                 // A k8-offset
    const int kb  = (lane >> 3) & 1;           // B k8-offset
    const uint32_t aRow0 = (uint32_t)((wm * 32 + (lane & 15)) * 1024);
    const uint32_t aRow1 = aRow0 + 16 * 1024;
    uint32_t bR[4];
#pragma unroll
    for (int j = 0; j < 4; j++)
        bR[j] = (uint32_t)((wn * 64 + j * 16 + x7 + ((lane >> 4) << 3)) * 128);

    float pr[2][2] = {{0.f, 0.f}, {0.f, 0.f}};        // layer-2 row partials

    for (int pass = 0; pass < 4; pass++) {
        const int l  = pass >> 1, nh = pass & 1;
        const char* wbase = (const char*)g_wprep + (size_t)pass * 8 * CHUNK_BYTES;
        const uint32_t u_A = (l == 0) ? u_Ain : u_Aout;

        float acc[2][8][4];
#pragma unroll
        for (int mg = 0; mg < 2; mg++)
#pragma unroll
            for (int ng = 0; ng < 8; ng++)
#pragma unroll
                for (int i = 0; i < 4; i++) acc[mg][ng][i] = 0.f;

        // stage chunk 0 via cp.async
        {
            const char* g = wbase + tid * 16;
            uint32_t d = u_W[0] + (uint32_t)tid * 16;
#pragma unroll
            for (int i = 0; i < 8; i++) CP16(d + i * 4096, g + i * 4096);
            CPCOMMIT(); CPWAIT0();
        }
        __syncthreads();   // also orders layer0 / previous epilogue A writes

        for (int c = 0; c < 8; c++) {
            if (c < 7) {   // stage chunk c+1 (overlaps MMA body below)
                const char* g = wbase + (size_t)(c + 1) * CHUNK_BYTES + tid * 16;
                uint32_t d = u_W[(c + 1) & 1] + (uint32_t)tid * 16;
#pragma unroll
                for (int i = 0; i < 8; i++) CP16(d + i * 4096, g + i * 4096);
                CPCOMMIT();
            }
            const uint32_t wb = u_W[c & 1];
#pragma unroll
            for (int ks = 0; ks < 4; ks++) {
                const int kbA = c * 8 + ks * 2 + ka;      // global k>>3
                const int kbB = ks * 2 + kb;              // chunk-local k>>3
                uint32_t a0r[4], a1r[4], br[4][4];
                LDSM4(a0r[0], a0r[1], a0r[2], a0r[3],
                      u_A + aRow0 + (uint32_t)((kbA ^ x7) << 4));
                LDSM4(a1r[0], a1r[1], a1r[2], a1r[3],
                      u_A + aRow1 + (uint32_t)((kbA ^ x7) << 4));
#pragma unroll
                for (int j = 0; j < 4; j++)
                    LDSM4(br[j][0], br[j][1], br[j][2], br[j][3],
                          wb + bR[j] + (uint32_t)((kbB ^ x7) << 4));
#pragma unroll
                for (int mg = 0; mg < 2; mg++) {
                    uint32_t* a = mg ? a1r : a0r;
#pragma unroll
                    for (int j = 0; j < 4; j++) {
                        MMA16816(acc[mg][2 * j],     a[0], a[1], a[2], a[3],
                                 br[j][0], br[j][1]);
                        MMA16816(acc[mg][2 * j + 1], a[0], a[1], a[2], a[3],
                                 br[j][2], br[j][3]);
                    }
                }
            }
            CPWAIT0();
            __syncthreads();
        }

        // -------- epilogue (adds layer bias, then silu) --------
        if (l == 0) {
#pragma unroll
            for (int mg = 0; mg < 2; mg++) {
                int rbase = wm * 32 + mg * 16 + (lane >> 2);
#pragma unroll
                for (int ng = 0; ng < 8; ng++) {
                    int nc = nh * 256 + wn * 64 + ng * 8 + 2 * (lane & 3);
                    float bb0 = sB1[nc], bb1 = sB1[nc + 1];
                    float v0 = silu(acc[mg][ng][0] + bb0);
                    float v1 = silu(acc[mg][ng][1] + bb1);
                    *(__half2*)(sAout + a_off(rbase, nc)) = __floats2half2_rn(v0, v1);
                    v0 = silu(acc[mg][ng][2] + bb0);
                    v1 = silu(acc[mg][ng][3] + bb1);
                    *(__half2*)(sAout + a_off(rbase + 8, nc)) = __floats2half2_rn(v0, v1);
                }
            }
        } else {
            // bias + silu + W3 dot folded into row partials (no SMEM round-trip)
#pragma unroll
            for (int mg = 0; mg < 2; mg++)
#pragma unroll
                for (int ng = 0; ng < 8; ng++) {
                    int nc = nh * 256 + wn * 64 + ng * 8 + 2 * (lane & 3);
                    float bb0 = sB2[nc], bb1 = sB2[nc + 1];
                    float w0 = sW3[nc],  w1 = sW3[nc + 1];
                    pr[mg][0] = fmaf(silu(acc[mg][ng][0] + bb0), w0, pr[mg][0]);
                    pr[mg][0] = fmaf(silu(acc[mg][ng][1] + bb1), w1, pr[mg][0]);
                    pr[mg][1] = fmaf(silu(acc[mg][ng][2] + bb0), w0, pr[mg][1]);
                    pr[mg][1] = fmaf(silu(acc[mg][ng][3] + bb1), w1, pr[mg][1]);
                }
        }
        __syncthreads();
    }

    // -------- final reduction: lanes (cols) -> warps (wn) -> rows --------
#pragma unroll
    for (int mg = 0; mg < 2; mg++)
#pragma unroll
        for (int h = 0; h < 2; h++) {
            float v = pr[mg][h];
            v += __shfl_xor_sync(0xffffffffu, v, 1);
            v += __shfl_xor_sync(0xffffffffu, v, 2);
            if ((lane & 3) == 0) {
                int r = wm * 32 + mg * 16 + (lane >> 2) + 8 * h;
                spart[r * 4 + wn] = v;
            }
        }
    __syncthreads();
    if (tid < MT) {
        float s = *sb3;
#pragma unroll
        for (int w = 0; w < 4; w++) s += spart[tid * 4 + w];
        out[m0 + tid] = s;
    }
}

// ---------------------------------------------------------------------------
extern "C" void kernel_launch(void* const* d_in, const int* in_sizes, int n_in,
                              void* d_out, int out_size) {
    const float* lat = (const float*)d_in[0];
    const float* W0  = (const float*)d_in[1];
    const float* b0  = (const float*)d_in[2];
    const float* W1  = (const float*)d_in[3];
    const float* b1  = (const float*)d_in[4];
    const float* W2  = (const float*)d_in[5];
    const float* b2  = (const float*)d_in[6];
    const float* W3  = (const float*)d_in[7];
    const float* b3  = (const float*)d_in[8];
    float* out = (float*)d_out;

    latb0_kernel<<<BATCH, HDIM>>>(lat, W0, b0);
    wprep_kernel<<<1024, 512>>>(W1, W2);

    size_t smem = 1024 + 203776 + 64;   // align slack + tiles + scalars
    cudaFuncSetAttribute(mlp_hmma_kernel,
                         cudaFuncAttributeMaxDynamicSharedMemorySize, (int)smem);
    mlp_hmma_kernel<<<NCTA, NT, smem>>>(W0, b1, b2, W3, b3, out);
}

// round 8
// speedup vs baseline: 7.1686x; 1.0884x over previous
#include <cuda_runtime.h>
#include <cuda_fp16.h>
#include <cstdint>

// ---------------------------------------------------------------------------
// ImplicitMeshDecoder via warp-level HMMA (mma.sync m16n8k16, fp16->fp32).
//   M = 524288 rows, H = 512.  Per CTA: 64 rows, 256 threads (8 warps).
//   Full-width N=512 sweep per layer, warp grid 1m x 8n (warp tile 64x64):
//   crossbar bytes/elem -33% vs half-sweeps, A read once per layer, and the
//   layer-1 output writes back IN-PLACE into the single 64KB A tile.
//   Weight chunks (512n x 64k = 64KB) double-buffered via cp.async.
//   layer0 : analytic coords + latent  -> silu -> A (SMEM fp16, XOR-swz)
//   layer1 : A @ W1 + b1  (HMMA)       -> silu -> A (in-place)
//   layer2 : A @ W2 + b2  (HMMA)       -> silu -> dot W3 (reg-folded) -> out
// ---------------------------------------------------------------------------

#define HDIM   512
#define MT     64
#define NT     256
#define PGRID  262144
#define BATCH  2
#define NCTA   ((BATCH * PGRID) / MT)    // 8192
#define CHUNK_HALFS 32768                // 512n * 64k
#define CHUNK_BYTES 65536

__device__ float  g_latb0[BATCH * HDIM];
__device__ __align__(16) __half g_wprep[2 * 8 * CHUNK_HALFS]; // [layer][kchunk][64KB]

// ---- helpers ---------------------------------------------------------------
static __device__ __forceinline__ uint32_t smem_u32(const void* p) {
    uint32_t a;
    asm("{ .reg .u64 t; cvta.to.shared.u64 t, %1; cvt.u32.u64 %0, t; }"
        : "=r"(a) : "l"(p));
    return a;
}
static __device__ __forceinline__ float silu(float v) {
    // exact-form silu (tanh.approx's ~1e-3 abs error would eat the gate)
    return __fdividef(v, 1.0f + __expf(-v));
}
// A tile (64 x 512 fp16, 1024B rows): byte for (r, k); XOR-permute 16B columns
static __device__ __forceinline__ uint32_t a_off(int r, int k) {
    return (uint32_t)(r * 1024) + (uint32_t)((((k >> 3) ^ (r & 7)) << 4))
         + (uint32_t)((k & 7) * 2);
}
// W chunk image (512n x 64k fp16, 128B rows): byte for (n, k)
static __device__ __forceinline__ uint32_t w_off(int n, int k) {
    return (uint32_t)(n * 128) + (uint32_t)(((k >> 3) ^ (n & 7)) << 4)
         + (uint32_t)((k & 7) * 2);
}

#define LDSM4(r0, r1, r2, r3, addr)                                        \
    asm volatile("ldmatrix.sync.aligned.m8n8.x4.shared.b16 "               \
                 "{%0,%1,%2,%3}, [%4];"                                    \
                 : "=r"(r0), "=r"(r1), "=r"(r2), "=r"(r3) : "r"(addr))

#define MMA16816(d, a0, a1, a2, a3, b0, b1)                                \
    asm volatile("mma.sync.aligned.m16n8k16.row.col.f32.f16.f16.f32 "      \
                 "{%0,%1,%2,%3}, {%4,%5,%6,%7}, {%8,%9}, {%0,%1,%2,%3};"   \
                 : "+f"((d)[0]), "+f"((d)[1]), "+f"((d)[2]), "+f"((d)[3])  \
                 : "r"(a0), "r"(a1), "r"(a2), "r"(a3), "r"(b0), "r"(b1))

#define CP16(dst, src) asm volatile(                                       \
    "cp.async.cg.shared.global [%0], [%1], 16;" :: "r"(dst), "l"(src))
#define CPCOMMIT() asm volatile("cp.async.commit_group;" ::: "memory")
#define CPWAIT0()  asm volatile("cp.async.wait_group 0;" ::: "memory")

// ---- prep: latb0 = latent @ W0[:512] + b0  (one warp per output) -----------
__global__ void latb0_kernel(const float* __restrict__ lat,
                             const float* __restrict__ W0,
                             const float* __restrict__ b0) {
    int wg   = blockIdx.x * 8 + (threadIdx.x >> 5);   // 0..1023
    int lane = threadIdx.x & 31;
    int b = wg >> 9, h = wg & 511;
    const float* L = lat + b * HDIM;
    float s = 0.f;
#pragma unroll
    for (int d = lane; d < HDIM; d += 32)
        s = fmaf(L[d], W0[d * HDIM + h], s);
#pragma unroll
    for (int o = 16; o; o >>= 1) s += __shfl_xor_sync(0xffffffffu, s, o);
    if (lane == 0) g_latb0[b * HDIM + h] = s + b0[h];
}

// ---- prep: W^T + fp16 + swizzle into chunk images --------------------------
// chunk (l, kc) holds WT[n = 0..511][k = kc*64 + kk]
__global__ void wprep_kernel(const float* __restrict__ W1,
                             const float* __restrict__ W2) {
    int idx = blockIdx.x * blockDim.x + threadIdx.x;   // 0 .. 2*512*512-1
    int l = idx >> 18, rem = idx & 262143;
    int k = rem >> 9, n = rem & 511;                   // source: W[k][n]
    float w = (l ? W2 : W1)[rem];
    int kc = k >> 6, kk = k & 63;
    g_wprep[(size_t)(l * 8 + kc) * CHUNK_HALFS + (w_off(n, kk) >> 1)]
        = __float2half_rn(w);
}

// ---- main fused kernel -----------------------------------------------------
__global__ __launch_bounds__(NT, 1)
void mlp_hmma_kernel(const float* __restrict__ W0,
                     const float* __restrict__ b1,
                     const float* __restrict__ b2,
                     const float* __restrict__ W3,
                     const float* __restrict__ b3,
                     float* __restrict__ out) {
    extern __shared__ char dyn[];
    uint32_t sbase = smem_u32(dyn);
    uint32_t s0 = (sbase + 1023u) & ~1023u;
    char* base = dyn + (s0 - sbase);

    char*  sA    = base;                       // 65536 (in-place across layers)
    float* sW3   = (float*)(base + 196608);    // 2048
    float* sB1   = (float*)(base + 198656);    // 2048
    float* sB2   = (float*)(base + 200704);    // 2048
    float* spart = (float*)(base + 202752);    // 2048 (64 rows x 8 warps)
    float* sb3   = (float*)(base + 204800);
    const uint32_t u_A = s0;
    const uint32_t u_W[2] = { s0 + 65536, s0 + 131072 };

    const int tid  = threadIdx.x;
    const int lane = tid & 31, wid = tid >> 5;   // wid = n-group (cols wid*64)
    const int m0   = blockIdx.x * MT;

    sW3[tid] = W3[tid];  sW3[tid + 256] = W3[tid + 256];
    sB1[tid] = b1[tid];  sB1[tid + 256] = b1[tid + 256];
    sB2[tid] = b2[tid];  sB2[tid + 256] = b2[tid + 256];
    if (tid == 0) *sb3 = b3[0];

    // -------- layer 0: analytic coords + latent -> silu -> A --------
    {
        const float* Wc = W0 + (size_t)HDIM * HDIM;
        const int b = m0 >> 18;
        const int n = tid * 2;                 // 256 threads x col-pair
        float la0 = g_latb0[b * HDIM + n],     la1 = g_latb0[b * HDIM + n + 1];
        float c00 = Wc[n],            c01 = Wc[n + 1];
        float c10 = Wc[HDIM + n],     c11 = Wc[HDIM + n + 1];
        float c20 = Wc[2 * HDIM + n], c21 = Wc[2 * HDIM + n + 1];
#pragma unroll 4
        for (int r = 0; r < MT; r++) {
            int p = (m0 + r) & (PGRID - 1);
            float x = -1.2f + (float)(p >> 12)       * (2.4f / 63.0f);
            float y = -1.2f + (float)((p >> 6) & 63) * (2.4f / 63.0f);
            float z = -1.2f + (float)(p & 63)        * (2.4f / 63.0f);
            float v0 = silu(fmaf(x, c00, fmaf(y, c10, fmaf(z, c20, la0))));
            float v1 = silu(fmaf(x, c01, fmaf(y, c11, fmaf(z, c21, la1))));
            *(__half2*)(sA + a_off(r, n)) = __floats2half2_rn(v0, v1);
        }
    }

    // per-lane ldmatrix addressing (invariant across layers)
    const int x7 = lane & 7;                   // XOR term (== row&7 everywhere)
    const int ka = lane >> 4;                  // A k8-offset
    const int kb = (lane >> 3) & 1;            // B k8-offset
    uint32_t aR[4], bR[4];
#pragma unroll
    for (int i = 0; i < 4; i++)
        aR[i] = (uint32_t)((i * 16 + (lane & 15)) * 1024);
#pragma unroll
    for (int j = 0; j < 4; j++)
        bR[j] = (uint32_t)((wid * 64 + j * 16 + x7 + ((lane >> 4) << 3)) * 128);

    float pr[4][2];                            // layer-2 row partials
#pragma unroll
    for (int mg = 0; mg < 4; mg++) { pr[mg][0] = 0.f; pr[mg][1] = 0.f; }

    for (int l = 0; l < 2; l++) {
        const char* wbase = (const char*)g_wprep + (size_t)l * 8 * CHUNK_BYTES;

        float acc[4][8][4];                    // 64m x 64n per warp = 128 regs
#pragma unroll
        for (int mg = 0; mg < 4; mg++)
#pragma unroll
            for (int ng = 0; ng < 8; ng++)
#pragma unroll
                for (int i = 0; i < 4; i++) acc[mg][ng][i] = 0.f;

        // stage chunk 0 via cp.async (64KB: 16 x 16B per thread)
        {
            const char* g = wbase + tid * 16;
            uint32_t d = u_W[0] + (uint32_t)tid * 16;
#pragma unroll
            for (int i = 0; i < 16; i++) CP16(d + i * 4096, g + i * 4096);
            CPCOMMIT(); CPWAIT0();
        }
        __syncthreads();   // orders layer0 / previous in-place A writes too

        for (int c = 0; c < 8; c++) {
            if (c < 7) {   // stage chunk c+1 (overlaps MMA body below)
                const char* g = wbase + (size_t)(c + 1) * CHUNK_BYTES + tid * 16;
                uint32_t d = u_W[(c + 1) & 1] + (uint32_t)tid * 16;
#pragma unroll
                for (int i = 0; i < 16; i++) CP16(d + i * 4096, g + i * 4096);
                CPCOMMIT();
            }
            const uint32_t wb = u_W[c & 1];
#pragma unroll
            for (int ks = 0; ks < 4; ks++) {
                const int kbA = c * 8 + ks * 2 + ka;      // global k>>3
                const int kbB = ks * 2 + kb;              // chunk-local k>>3
                uint32_t ar[4][4], br[4][4];
#pragma unroll
                for (int i = 0; i < 4; i++)
                    LDSM4(ar[i][0], ar[i][1], ar[i][2], ar[i][3],
                          u_A + aR[i] + (uint32_t)((kbA ^ x7) << 4));
#pragma unroll
                for (int j = 0; j < 4; j++)
                    LDSM4(br[j][0], br[j][1], br[j][2], br[j][3],
                          wb + bR[j] + (uint32_t)((kbB ^ x7) << 4));
#pragma unroll
                for (int mg = 0; mg < 4; mg++) {
                    // each ar[] LDSM4 covers 16 rows x k16
                    int i = mg;
#pragma unroll
                    for (int j = 0; j < 4; j++) {
                        MMA16816(acc[mg][2 * j],     ar[i][0], ar[i][1],
                                 ar[i][2], ar[i][3], br[j][0], br[j][1]);
                        MMA16816(acc[mg][2 * j + 1], ar[i][0], ar[i][1],
                                 ar[i][2], ar[i][3], br[j][2], br[j][3]);
                    }
                }
            }
            CPWAIT0();
            __syncthreads();   // after last chunk: all A reads complete
        }

        // -------- epilogue (adds layer bias, then silu) --------
        if (l == 0) {
            // in-place writeback: safe, k-loop ended with __syncthreads()
#pragma unroll
            for (int mg = 0; mg < 4; mg++) {
                int rbase = mg * 16 + (lane >> 2);
#pragma unroll
                for (int ng = 0; ng < 8; ng++) {
                    int nc = wid * 64 + ng * 8 + 2 * (lane & 3);
                    float bb0 = sB1[nc], bb1 = sB1[nc + 1];
                    float v0 = silu(acc[mg][ng][0] + bb0);
                    float v1 = silu(acc[mg][ng][1] + bb1);
                    *(__half2*)(sA + a_off(rbase, nc)) = __floats2half2_rn(v0, v1);
                    v0 = silu(acc[mg][ng][2] + bb0);
                    v1 = silu(acc[mg][ng][3] + bb1);
                    *(__half2*)(sA + a_off(rbase + 8, nc)) = __floats2half2_rn(v0, v1);
                }
            }
        } else {
            // bias + silu + W3 dot folded into row partials
#pragma unroll
            for (int mg = 0; mg < 4; mg++)
#pragma unroll
                for (int ng = 0; ng < 8; ng++) {
                    int nc = wid * 64 + ng * 8 + 2 * (lane & 3);
                    float bb0 = sB2[nc], bb1 = sB2[nc + 1];
                    float w0 = sW3[nc],  w1 = sW3[nc + 1];
                    pr[mg][0] = fmaf(silu(acc[mg][ng][0] + bb0), w0, pr[mg][0]);
                    pr[mg][0] = fmaf(silu(acc[mg][ng][1] + bb1), w1, pr[mg][0]);
                    pr[mg][1] = fmaf(silu(acc[mg][ng][2] + bb0), w0, pr[mg][1]);
                    pr[mg][1] = fmaf(silu(acc[mg][ng][3] + bb1), w1, pr[mg][1]);
                }
        }
        __syncthreads();
    }

    // -------- final reduction: lanes (cols) -> warps -> rows --------
#pragma unroll
    for (int mg = 0; mg < 4; mg++)
#pragma unroll
        for (int h = 0; h < 2; h++) {
            float v = pr[mg][h];
            v += __shfl_xor_sync(0xffffffffu, v, 1);
            v += __shfl_xor_sync(0xffffffffu, v, 2);
            if ((lane & 3) == 0) {
                int r = mg * 16 + (lane >> 2) + 8 * h;
                spart[r * 8 + wid] = v;
            }
        }
    __syncthreads();
    if (tid < MT) {
        float s = *sb3;
#pragma unroll
        for (int w = 0; w < 8; w++) s += spart[tid * 8 + w];
        out[m0 + tid] = s;
    }
}

// ---------------------------------------------------------------------------
extern "C" void kernel_launch(void* const* d_in, const int* in_sizes, int n_in,
                              void* d_out, int out_size) {
    const float* lat = (const float*)d_in[0];
    const float* W0  = (const float*)d_in[1];
    const float* b0  = (const float*)d_in[2];
    const float* W1  = (const float*)d_in[3];
    const float* b1  = (const float*)d_in[4];
    const float* W2  = (const float*)d_in[5];
    const float* b2  = (const float*)d_in[6];
    const float* W3  = (const float*)d_in[7];
    const float* b3  = (const float*)d_in[8];
    float* out = (float*)d_out;

    latb0_kernel<<<128, 256>>>(lat, W0, b0);        // 1024 warps = 1024 outputs
    wprep_kernel<<<1024, 512>>>(W1, W2);

    size_t smem = 1024 + 204800 + 64;   // align slack + A + 2 Wbuf + scalars
    cudaFuncSetAttribute(mlp_hmma_kernel,
                         cudaFuncAttributeMaxDynamicSharedMemorySize, (int)smem);
    mlp_hmma_kernel<<<NCTA, NT, smem>>>(W0, b1, b2, W3, b3, out);
}